// round 12
// baseline (speedup 1.0000x reference)
#include <cuda_runtime.h>
#include <cuda_bf16.h>

// BoundaryLoss: mean(sigmoid(logits) * EDT2D(target)), [8,1,256,256].
//
// SINGLE kernel, 512 CTAs x 256 thr, __launch_bounds__(256,4) => >=4 CTAs/SM
// resident => all 512 CTAs co-resident in wave 1 => software grid barrier is
// deadlock-free while keeping the full 4096-warp pool.
//   Phase 1: CTA c scans its 4 rows [4c,4c+4) (warps 0..3, shuffle scans,
//            zero redundancy) -> g_dr2. ALL threads prefetch their phase-2
//            logits float4 + sigmoid (DRAM latency hidden here).
//   Barrier: monotonic-epoch atomic counter (graph-replay safe).
//   Phase 2: R5's proven float4 window min (9 vector loads, j in [i-4,i+4])
//            + rare exact expand tail; block reduce + one atomicAdd/CTA.

#define B 8
#define H 256
#define W 256
#define NPIX (B * H * W)          // 524288
#define NV4  (NPIX / 4)           // 131072 float4 tasks
#define BIGD 1000000.0f
#define FULL 0xffffffffu
#define RW4 (W / 4)               // 64 float4 per row
#define NBLK 512

__device__ float    g_dr2[NPIX];
__device__ unsigned g_bar = 0u;   // monotonic across graph replays

__device__ __forceinline__ float4 fmin4a(float4 a, float4 bu, float4 bd, float rr)
{
    a.x = fminf(a.x, fminf(bu.x, bd.x) + rr);
    a.y = fminf(a.y, fminf(bu.y, bd.y) + rr);
    a.z = fminf(a.z, fminf(bu.z, bd.z) + rr);
    a.w = fminf(a.w, fminf(bu.w, bd.w) + rr);
    return a;
}

__global__ __launch_bounds__(256, 4)
void k_fused(const float* __restrict__ logits,
             const int* __restrict__ target,
             float* __restrict__ out)
{
    const int tid  = threadIdx.x;
    const int lane = tid & 31;
    const int warp = tid >> 5;
    const int c    = blockIdx.x;

    if (c == 0 && tid == 0) *out = 0.0f;

    // ---- prefetch phase-2 logits (overlaps row scan + barrier) ----
    const int v = c * 256 + tid;                   // this thread's f4 task
    const float4 xv = reinterpret_cast<const float4*>(logits)[v];
    const float px = 1.0f / (1.0f + __expf(-xv.x));
    const float py = 1.0f / (1.0f + __expf(-xv.y));
    const float pz = 1.0f / (1.0f + __expf(-xv.z));
    const float pw = 1.0f / (1.0f + __expf(-xv.w));

    // ================= Phase 1: row distances (warps 0..3) =================
    if (warp < 4) {
        const int row  = c * 4 + warp;             // 0..2047
        const int base = row * W;
        const int w0   = lane << 3;                // 8 px per lane

        const int4* tp = reinterpret_cast<const int4*>(target + base + w0);
        const int4 t0 = tp[0];
        const int4 t1 = tp[1];
        int fg[8];
        fg[0] = t0.x > 0; fg[1] = t0.y > 0; fg[2] = t0.z > 0; fg[3] = t0.w > 0;
        fg[4] = t1.x > 0; fg[5] = t1.y > 0; fg[6] = t1.z > 0; fg[7] = t1.w > 0;

        // nearest fg <= w : prefix max of (fg? w : -1)
        int pl[8];
        int run = -1;
#pragma unroll
        for (int k = 0; k < 8; ++k) {
            const int cand = fg[k] ? (w0 + k) : -1;
            run = max(run, cand);
            pl[k] = run;
        }
        int x = run;
#pragma unroll
        for (int off = 1; off < 32; off <<= 1) {
            const int y = __shfl_up_sync(FULL, x, off);
            if (lane >= off) x = max(x, y);
        }
        int exl = __shfl_up_sync(FULL, x, 1);
        if (lane == 0) exl = -1;

        // nearest fg >= w : suffix min of (fg? w : 512)
        int pr[8];
        int run2 = 512;
#pragma unroll
        for (int k = 7; k >= 0; --k) {
            const int cand = fg[k] ? (w0 + k) : 512;
            run2 = min(run2, cand);
            pr[k] = run2;
        }
        int x2 = run2;
#pragma unroll
        for (int off = 1; off < 32; off <<= 1) {
            const int y = __shfl_down_sync(FULL, x2, off);
            if (lane + off < 32) x2 = min(x2, y);
        }
        int exr = __shfl_down_sync(FULL, x2, 1);
        if (lane == 31) exr = 512;

        float o[8];
#pragma unroll
        for (int k = 0; k < 8; ++k) {
            const int L = max(pl[k], exl);
            const int R = min(pr[k], exr);
            const float dl = (L >= 0)  ? (float)(w0 + k - L) : BIGD;
            const float dr = (R < 512) ? (float)(R - (w0 + k)) : BIGD;
            const float d  = fminf(dl, dr);
            o[k] = d * d;
        }
        float4* op = reinterpret_cast<float4*>(g_dr2 + base + w0);
        op[0] = make_float4(o[0], o[1], o[2], o[3]);
        op[1] = make_float4(o[4], o[5], o[6], o[7]);
    }

    // ================= Grid barrier (epoch-based, replay-safe) =============
    __threadfence();              // release: dr2 + *out visible device-wide
    __syncthreads();
    if (tid == 0) {
        const unsigned prev = atomicAdd(&g_bar, 1u);
        const unsigned tgt  = (prev / NBLK + 1u) * NBLK;
        while (*(volatile unsigned*)&g_bar < tgt) { }
    }
    __syncthreads();
    __threadfence();              // acquire

    // ================= Phase 2: column EDT + loss =================
    const int i = (v / RW4) & (H - 1);             // row within image

    const float4* dr  = reinterpret_cast<const float4*>(g_dr2);
    const float4  big = make_float4(BIGD, BIGD, BIGD, BIGD);

    float4 cur = dr[v];
    const float4 u1 = (i >= 1)    ? dr[v - 1 * RW4] : big;
    const float4 d1 = (i + 1 < H) ? dr[v + 1 * RW4] : big;
    const float4 u2 = (i >= 2)    ? dr[v - 2 * RW4] : big;
    const float4 d2 = (i + 2 < H) ? dr[v + 2 * RW4] : big;
    const float4 u3 = (i >= 3)    ? dr[v - 3 * RW4] : big;
    const float4 d3 = (i + 3 < H) ? dr[v + 3 * RW4] : big;
    const float4 u4 = (i >= 4)    ? dr[v - 4 * RW4] : big;
    const float4 d4 = (i + 4 < H) ? dr[v + 4 * RW4] : big;

    cur = fmin4a(cur, u1, d1, 1.0f);
    cur = fmin4a(cur, u2, d2, 4.0f);
    cur = fmin4a(cur, u3, d3, 9.0f);
    cur = fmin4a(cur, u4, d4, 16.0f);

    // rare exact tail: r >= 5, scalar per component
    if (fmaxf(fmaxf(cur.x, cur.y), fmaxf(cur.z, cur.w)) > 25.0f) {
        float* cc = &cur.x;
        const int p0 = v << 2;
#pragma unroll
        for (int q = 0; q < 4; ++q) {
            for (int r = 5; r < H && (float)(r * r) < cc[q]; ++r) {
                const float rr = (float)(r * r);
                if (i >= r)    cc[q] = fminf(cc[q], g_dr2[p0 + q - (r << 8)] + rr);
                if (i + r < H) cc[q] = fminf(cc[q], g_dr2[p0 + q + (r << 8)] + rr);
            }
        }
    }

    float val = px * sqrtf(cur.x) + py * sqrtf(cur.y)
              + pz * sqrtf(cur.z) + pw * sqrtf(cur.w);
    val *= (1.0f / (float)NPIX);

    // block reduction -> one atomic per CTA
#pragma unroll
    for (int o = 16; o; o >>= 1)
        val += __shfl_xor_sync(FULL, val, o);

    __shared__ float ws[8];
    if (lane == 0) ws[warp] = val;
    __syncthreads();
    if (tid == 0) {
        float t = ws[0];
#pragma unroll
        for (int k = 1; k < 8; ++k) t += ws[k];
        atomicAdd(out, t);
    }
}

extern "C" void kernel_launch(void* const* d_in, const int* in_sizes, int n_in,
                              void* d_out, int out_size)
{
    const float* logits = (const float*)d_in[0];
    const int*   target = (const int*)d_in[1];
    float*       out    = (float*)d_out;

    k_fused<<<NBLK, 256>>>(logits, target, out);
}

// round 13
// speedup vs baseline: 1.2694x; 1.2694x over previous
#include <cuda_runtime.h>
#include <cuda_bf16.h>

// BoundaryLoss: mean(sigmoid(logits) * EDT2D(target)), [8,1,256,256].
//
// Two kernels (all fusion variants measured slower; launch overhead ~1us).
// Stage 1 (k_rowdist): warp-per-row exact 1D row distance^2 (shuffle scans).
// Stage 2 (k_edt_loss): 1 thread = 2 px (float2), grid 1024 -> 8192 warps
//   (~55/SM) to cover L2 latency of the 9-row batched window
//   D2(i,w) = min_j dr2[j,w] + (i-j)^2, j in [i-4,i+4], + rare exact tail.
//   Fused sigmoid + block reduce + one atomicAdd per CTA.

#define B 8
#define H 256
#define W 256
#define NPIX (B * H * W)          // 524288
#define NV2  (NPIX / 2)           // 262144 float2 tasks
#define BIGD 1000000.0f
#define FULL 0xffffffffu
#define RW2 (W / 2)               // 128 float2 per row

__device__ float g_dr2[NPIX];     // squared 1D row distances

__global__ void k_rowdist(const int* __restrict__ target,
                          float* __restrict__ out)
{
    if (blockIdx.x == 0 && threadIdx.x == 0) *out = 0.0f;

    const int lane = threadIdx.x & 31;
    const int warp = threadIdx.x >> 5;
    const int row  = (blockIdx.x << 3) + warp;     // 8 rows per block
    const int base = row * W;
    const int w0   = lane << 3;                    // 8 px per lane

    const int4* tp = reinterpret_cast<const int4*>(target + base + w0);
    const int4 t0 = tp[0];
    const int4 t1 = tp[1];
    int fg[8];
    fg[0] = t0.x > 0; fg[1] = t0.y > 0; fg[2] = t0.z > 0; fg[3] = t0.w > 0;
    fg[4] = t1.x > 0; fg[5] = t1.y > 0; fg[6] = t1.z > 0; fg[7] = t1.w > 0;

    // nearest fg <= w : prefix max of (fg? w : -1)
    int pl[8];
    int run = -1;
#pragma unroll
    for (int k = 0; k < 8; ++k) {
        const int cand = fg[k] ? (w0 + k) : -1;
        run = max(run, cand);
        pl[k] = run;
    }
    int x = run;
#pragma unroll
    for (int off = 1; off < 32; off <<= 1) {
        const int y = __shfl_up_sync(FULL, x, off);
        if (lane >= off) x = max(x, y);
    }
    int exl = __shfl_up_sync(FULL, x, 1);
    if (lane == 0) exl = -1;

    // nearest fg >= w : suffix min of (fg? w : 512)
    int pr[8];
    int run2 = 512;
#pragma unroll
    for (int k = 7; k >= 0; --k) {
        const int cand = fg[k] ? (w0 + k) : 512;
        run2 = min(run2, cand);
        pr[k] = run2;
    }
    int x2 = run2;
#pragma unroll
    for (int off = 1; off < 32; off <<= 1) {
        const int y = __shfl_down_sync(FULL, x2, off);
        if (lane + off < 32) x2 = min(x2, y);
    }
    int exr = __shfl_down_sync(FULL, x2, 1);
    if (lane == 31) exr = 512;

    float o[8];
#pragma unroll
    for (int k = 0; k < 8; ++k) {
        const int L = max(pl[k], exl);
        const int R = min(pr[k], exr);
        const float dl = (L >= 0)  ? (float)(w0 + k - L) : BIGD;
        const float dr = (R < 512) ? (float)(R - (w0 + k)) : BIGD;
        const float d  = fminf(dl, dr);
        o[k] = d * d;
    }
    float4* op = reinterpret_cast<float4*>(g_dr2 + base + w0);
    op[0] = make_float4(o[0], o[1], o[2], o[3]);
    op[1] = make_float4(o[4], o[5], o[6], o[7]);
}

__device__ __forceinline__ float2 fmin2a(float2 a, float2 bu, float2 bd, float rr)
{
    a.x = fminf(a.x, fminf(bu.x, bd.x) + rr);
    a.y = fminf(a.y, fminf(bu.y, bd.y) + rr);
    return a;
}

__global__ __launch_bounds__(256)
void k_edt_loss(const float* __restrict__ logits,
                float* __restrict__ out)
{
    const int v = blockIdx.x * blockDim.x + threadIdx.x;   // float2 task
    const int i = (v / RW2) & (H - 1);                     // row within image

    const float2* dr  = reinterpret_cast<const float2*>(g_dr2);
    const float2  xv  = reinterpret_cast<const float2*>(logits)[v];
    const float2  big = make_float2(BIGD, BIGD);

    // batch phase: 9 independent loads covering j in [i-4, i+4]
    float2 cur = dr[v];
    const float2 u1 = (i >= 1)    ? dr[v - 1 * RW2] : big;
    const float2 d1 = (i + 1 < H) ? dr[v + 1 * RW2] : big;
    const float2 u2 = (i >= 2)    ? dr[v - 2 * RW2] : big;
    const float2 d2 = (i + 2 < H) ? dr[v + 2 * RW2] : big;
    const float2 u3 = (i >= 3)    ? dr[v - 3 * RW2] : big;
    const float2 d3 = (i + 3 < H) ? dr[v + 3 * RW2] : big;
    const float2 u4 = (i >= 4)    ? dr[v - 4 * RW2] : big;
    const float2 d4 = (i + 4 < H) ? dr[v + 4 * RW2] : big;

    cur = fmin2a(cur, u1, d1, 1.0f);
    cur = fmin2a(cur, u2, d2, 4.0f);
    cur = fmin2a(cur, u3, d3, 9.0f);
    cur = fmin2a(cur, u4, d4, 16.0f);

    // rare exact tail: r >= 5, scalar per component
    if (fmaxf(cur.x, cur.y) > 25.0f) {
        float* c = &cur.x;
        const int p0 = v << 1;
#pragma unroll
        for (int q = 0; q < 2; ++q) {
            for (int r = 5; r < H && (float)(r * r) < c[q]; ++r) {
                const float rr = (float)(r * r);
                if (i >= r)    c[q] = fminf(c[q], g_dr2[p0 + q - (r << 8)] + rr);
                if (i + r < H) c[q] = fminf(c[q], g_dr2[p0 + q + (r << 8)] + rr);
            }
        }
    }

    const float px = 1.0f / (1.0f + __expf(-xv.x));
    const float py = 1.0f / (1.0f + __expf(-xv.y));

    float val = (px * sqrtf(cur.x) + py * sqrtf(cur.y)) * (1.0f / (float)NPIX);

    // block reduction -> one atomic per CTA
#pragma unroll
    for (int o = 16; o; o >>= 1)
        val += __shfl_xor_sync(FULL, val, o);

    __shared__ float ws[8];
    if ((threadIdx.x & 31) == 0) ws[threadIdx.x >> 5] = val;
    __syncthreads();
    if (threadIdx.x == 0) {
        float t = ws[0];
#pragma unroll
        for (int k = 1; k < 8; ++k) t += ws[k];
        atomicAdd(out, t);
    }
}

extern "C" void kernel_launch(void* const* d_in, const int* in_sizes, int n_in,
                              void* d_out, int out_size)
{
    const float* logits = (const float*)d_in[0];
    const int*   target = (const int*)d_in[1];
    float*       out    = (float*)d_out;

    k_rowdist<<<(B * H) / 8, 256>>>(target, out);
    k_edt_loss<<<NV2 / 256, 256>>>(logits, out);
}